// round 5
// baseline (speedup 1.0000x reference)
#include <cuda_runtime.h>
#include <cstddef>
#include <cstdint>

// Problem constants: B=2, S=512, H=256, A=128
#define BB 2
#define SS 512
#define HH 256
#define AA 128
#define HCH 8          // h-columns per scan block
#define XPAD 516       // smem row pitch: 516 % 32 == 4 -> conflict-free transpose

// Scratch (device globals; no allocs allowed)
__device__ float g_s[BB * SS];          // raw scores s[b,j]
__device__ float g_w[BB * SS];          // e_j * am_j
__device__ float g_scale[BB * SS];      // am_i / C_i

// ---------------------------------------------------------------------------
// Kernel 1: s[b,j] = sum_a query[a] * tanh( sum_h x[b,j,h] * w_a[h,a] )
// grid 128 (8 rows/block), block 512 (16 warps).
// warp = (row-pair p = wid&3, h-group g = wid>>2, 64 h each).
// w loads: two-deep double-buffered asm-volatile LDG.128 (forced MLP=8).
// ---------------------------------------------------------------------------
__global__ __launch_bounds__(512) void k_score(
    const float* __restrict__ x, const float* __restrict__ w_a,
    const float* __restrict__ query)
{
    __shared__ float xsT[HH * 8];            // xsT[h*8 + r]
    __shared__ float sred[8][5][AA];         // [row][g(pad 5)][col]
    const int tid  = threadIdx.x;
    const int lane = tid & 31;
    const int wid  = tid >> 5;
    const int p    = wid & 3;
    const int g    = wid >> 2;
    const int r0   = blockIdx.x * 8;

    // stage 8 rows of x transposed
    {
        const int r  = tid & 7;
        const int h4 = tid >> 3;             // 0..63
        const float4 v =
            reinterpret_cast<const float4*>(x + (size_t)r0 * HH)[r * 64 + h4];
        xsT[(h4 * 4 + 0) * 8 + r] = v.x;
        xsT[(h4 * 4 + 1) * 8 + r] = v.y;
        xsT[(h4 * 4 + 2) * 8 + r] = v.z;
        xsT[(h4 * 4 + 3) * 8 + r] = v.w;
    }
    __syncthreads();

    float a00=0.f,a01=0.f,a02=0.f,a03=0.f,a10=0.f,a11=0.f,a12=0.f,a13=0.f;
    const int h0 = g * 64;
    const float* wp = w_a + (size_t)h0 * AA + lane * 4;
    const float* xp = xsT + h0 * 8 + 2 * p;

    float4 bufA[8], bufB[8];

#define LDW(dst, off)                                                        \
    asm volatile("ld.global.nc.v4.f32 {%0,%1,%2,%3}, [%4];"                  \
        : "=f"((dst).x), "=f"((dst).y), "=f"((dst).z), "=f"((dst).w)         \
        : "l"(wp + (size_t)(off) * AA))

#define COMPUTE(buf, c)                                                      \
    _Pragma("unroll")                                                        \
    for (int u = 0; u < 8; ++u) {                                            \
        const float2 x2 =                                                    \
            *reinterpret_cast<const float2*>(xp + (size_t)((c) * 8 + u) * 8);\
        const float4 w4 = (buf)[u];                                          \
        a00 += x2.x * w4.x; a01 += x2.x * w4.y;                              \
        a02 += x2.x * w4.z; a03 += x2.x * w4.w;                              \
        a10 += x2.y * w4.x; a11 += x2.y * w4.y;                              \
        a12 += x2.y * w4.z; a13 += x2.y * w4.w;                              \
    }

#pragma unroll
    for (int u = 0; u < 8; ++u) LDW(bufA[u], u);

#pragma unroll
    for (int c = 0; c < 8; c += 2) {
        if (c + 1 < 8) {
#pragma unroll
            for (int u = 0; u < 8; ++u) LDW(bufB[u], (c + 1) * 8 + u);
        }
        COMPUTE(bufA, c);
        if (c + 1 < 8) {
            if (c + 2 < 8) {
#pragma unroll
                for (int u = 0; u < 8; ++u) LDW(bufA[u], (c + 2) * 8 + u);
            }
            COMPUTE(bufB, c + 1);
        }
    }
#undef LDW
#undef COMPUTE

    *reinterpret_cast<float4*>(&sred[2 * p + 0][g][lane * 4]) =
        make_float4(a00, a01, a02, a03);
    *reinterpret_cast<float4*>(&sred[2 * p + 1][g][lane * 4]) =
        make_float4(a10, a11, a12, a13);
    __syncthreads();

    if (wid < 8) {
        const float4 q4 = reinterpret_cast<const float4*>(query)[lane];
        const float4 v0 = *reinterpret_cast<const float4*>(&sred[wid][0][lane * 4]);
        const float4 v1 = *reinterpret_cast<const float4*>(&sred[wid][1][lane * 4]);
        const float4 v2 = *reinterpret_cast<const float4*>(&sred[wid][2][lane * 4]);
        const float4 v3 = *reinterpret_cast<const float4*>(&sred[wid][3][lane * 4]);
        const float c0 = v0.x + v1.x + v2.x + v3.x;
        const float c1 = v0.y + v1.y + v2.y + v3.y;
        const float c2 = v0.z + v1.z + v2.z + v3.z;
        const float c3 = v0.w + v1.w + v2.w + v3.w;
        float s = q4.x * tanhf(c0) + q4.y * tanhf(c1)
                + q4.z * tanhf(c2) + q4.w * tanhf(c3);
#pragma unroll
        for (int o = 16; o > 0; o >>= 1) s += __shfl_down_sync(0xffffffffu, s, o);
        if (lane == 0) g_s[r0 + wid] = s;
    }
}

// ---------------------------------------------------------------------------
// Kernel 2: per-batch max + exp + inclusive prefix sum (shfl warp scans).
// ---------------------------------------------------------------------------
__global__ __launch_bounds__(512) void k_scan(const int* __restrict__ amask)
{
    const int b = blockIdx.x, tid = threadIdx.x;
    const int lane = tid & 31, wid = tid >> 5;   // 16 warps
    __shared__ float wmax[16], wsum[16];

    const float sv = g_s[b * SS + tid];

    float m = sv;
#pragma unroll
    for (int o = 16; o > 0; o >>= 1) m = fmaxf(m, __shfl_xor_sync(0xffffffffu, m, o));
    if (lane == 0) wmax[wid] = m;
    __syncthreads();
    float M = wmax[0];
#pragma unroll
    for (int k = 1; k < 16; ++k) M = fmaxf(M, wmax[k]);

    const float e = expf(sv - M);

    float sc = e;
#pragma unroll
    for (int o = 1; o < 32; o <<= 1) {
        const float t = __shfl_up_sync(0xffffffffu, sc, o);
        if (lane >= o) sc += t;
    }
    if (lane == 31) wsum[wid] = sc;
    __syncthreads();
    float off = 0.f;
#pragma unroll
    for (int k = 0; k < 16; ++k)
        if (k < wid) off += wsum[k];

    const float C  = sc + off;
    const int   am = amask[b * SS + tid];
    g_w[b * SS + tid]     = am ? e : 0.f;
    g_scale[b * SS + tid] = am ? (1.f / C) : 0.f;
}

// ---------------------------------------------------------------------------
// Kernel 3 (fused): grid (256 + 32, B), 512 threads.
//  bx < 256 : write 2 rows of d (float2 stores).
//  bx >= 256: column-scan block computing a[b, :, h0..h0+7] directly.
//    - stage x[b, :, h0..h0+7] transposed in smem (coalesced, conflict-free)
//    - 16 warps: 2 per h-column, each scans 256 j via 8x shfl-scan + carry
//    - halves combined via smem total, result written back coalesced
// ---------------------------------------------------------------------------
__global__ __launch_bounds__(512) void k_fused(
    const float* __restrict__ x, float* __restrict__ d_out,
    float* __restrict__ a_out)
{
    const int b = blockIdx.y, tid = threadIdx.x;

    if (blockIdx.x < 256) {
        const int rp = tid >> 8;             // 0/1
        const int sl = tid & 255;            // float2 slot
        const int i  = blockIdx.x * 2 + rp;
        const float sc = g_scale[b * SS + i];
        const float2 w2 = reinterpret_cast<const float2*>(g_w + b * SS)[sl];
        const int j0 = sl * 2;
        float2 o;
        o.x = (j0     <= i) ? w2.x * sc : 0.f;
        o.y = (j0 + 1 <= i) ? w2.y * sc : 0.f;
        reinterpret_cast<float2*>(d_out + (size_t)(b * SS + i) * SS)[sl] = o;
        return;
    }

    // ---- a-scan part ----
    __shared__ float xt[HCH][XPAD];
    __shared__ float ws[SS], scs[SS];
    __shared__ float htot[HCH];

    const int h0 = (blockIdx.x - 256) * HCH;

    ws[tid]  = g_w[b * SS + tid];
    scs[tid] = g_scale[b * SS + tid];

    const float* xb = x + (size_t)b * SS * HH + h0;
#pragma unroll
    for (int it = 0; it < HCH; ++it) {
        const int flat = it * 512 + tid;     // 0..4095
        const int j  = flat >> 3;
        const int hh = flat & 7;
        xt[hh][j] = xb[(size_t)j * HH + hh];
    }
    __syncthreads();

    const int lane = tid & 31, wid = tid >> 5;
    const int hh   = wid >> 1;               // h-column 0..7
    const int half = wid & 1;                // j-half 0/1
    const int jb   = half * 256;

    float carry = 0.f;
    float vals[8];
#pragma unroll
    for (int k = 0; k < 8; ++k) {
        const int j = jb + k * 32 + lane;
        float v = xt[hh][j] * ws[j];
#pragma unroll
        for (int o = 1; o < 32; o <<= 1) {
            const float t = __shfl_up_sync(0xffffffffu, v, o);
            if (lane >= o) v += t;
        }
        v += carry;
        carry = __shfl_sync(0xffffffffu, v, 31);
        vals[k] = v;
    }
    if (half == 0 && lane == 31) htot[hh] = carry;
    __syncthreads();

    const float base = half ? htot[hh] : 0.f;
#pragma unroll
    for (int k = 0; k < 8; ++k) {
        const int j = jb + k * 32 + lane;
        xt[hh][j] = (vals[k] + base) * scs[j];
    }
    __syncthreads();

    float* ab = a_out + (size_t)b * SS * HH + h0;
#pragma unroll
    for (int it = 0; it < HCH; ++it) {
        const int flat = it * 512 + tid;
        const int j  = flat >> 3;
        const int h2 = flat & 7;
        ab[(size_t)j * HH + h2] = xt[h2][j];
    }
}

// ---------------------------------------------------------------------------
extern "C" void kernel_launch(void* const* d_in, const int* in_sizes, int n_in,
                              void* d_out, int out_size)
{
    const float* x     = (const float*)d_in[0];   // (B,S,H)
    const int*   amask = (const int*)  d_in[1];   // (B,S)
    const float* w_a   = (const float*)d_in[2];   // (H,A)
    const float* query = (const float*)d_in[3];   // (A,)

    float* out   = (float*)d_out;
    float* a_out = out;                                // (B,S,H) first
    float* dd    = out + (size_t)BB * SS * HH;         // (B,S,S) second

    k_score<<<(BB * SS) / 8, 512>>>(x, w_a, query);
    k_scan<<<BB, SS>>>(amask);
    k_fused<<<dim3(256 + HH / HCH, BB), 512>>>(x, dd, a_out);
}